// round 6
// baseline (speedup 1.0000x reference)
#include <cuda_runtime.h>
#include <cuda_fp16.h>
#include <math.h>

// Sinkhorn distance: B=16, Lx=Ly=1024, D=256, eps=0.1, 50 iters.
// Log-domain in log2 units: lk2 = -cost*(10/ln2), log_mu2 = log_nu2 = -10.
// Cost matrix stored in fp16 TWICE (row-major + transposed) so both LSE sweep
// directions are warp-per-contiguous-line; both copies (64 MB) stay L2-resident.
// All 50 iterations + transport + reduce in ONE persistent kernel (512 blocks,
// software grid barrier).

#define BATCH 16
#define LSEQ  1024
#define DDIM  256
#define K2C   14.426950408889634f   // 10 / ln(2)
#define NBLK  512
#define NTHR  256

__device__ __half g_ch[(size_t)BATCH * LSEQ * LSEQ];  // 32 MB row-major cost
__device__ __half g_ct[(size_t)BATCH * LSEQ * LSEQ];  // 32 MB transposed cost
__device__ float g_x2[BATCH * LSEQ];
__device__ float g_y2[BATCH * LSEQ];
__device__ float g_lu[BATCH * LSEQ];
__device__ float g_lv[BATCH * LSEQ];
__device__ float g_part[NBLK];
__device__ unsigned g_bar_cnt = 0;
__device__ unsigned g_bar_gen = 0;

static __device__ __forceinline__ float ex2f(float x) {
    float r; asm("ex2.approx.ftz.f32 %0, %1;" : "=f"(r) : "f"(x)); return r;
}
static __device__ __forceinline__ float lg2f(float x) {
    float r; asm("lg2.approx.ftz.f32 %0, %1;" : "=f"(r) : "f"(x)); return r;
}

typedef unsigned long long ull;
static __device__ __forceinline__ ull pack2(float lo, float hi) {
    ull r; asm("mov.b64 %0, {%1, %2};" : "=l"(r) : "f"(lo), "f"(hi)); return r;
}
static __device__ __forceinline__ float2 unpack2(ull v) {
    float2 r; asm("mov.b64 {%0, %1}, %2;" : "=f"(r.x), "=f"(r.y) : "l"(v)); return r;
}
static __device__ __forceinline__ void ffma2(ull& d, ull a, ull b) {
    asm("fma.rn.f32x2 %0, %1, %2, %0;" : "+l"(d) : "l"(a), "l"(b));
}

// Sense-reversing grid barrier (512 blocks; launch_bounds(256,4) -> 592 slots).
static __device__ __forceinline__ void grid_barrier() {
    __syncthreads();
    if (threadIdx.x == 0) {
        __threadfence();
        unsigned gen = *(volatile unsigned*)&g_bar_gen;
        unsigned prev = atomicAdd(&g_bar_cnt, 1u);
        if (prev == NBLK - 1) {
            g_bar_cnt = 0;
            __threadfence();
            *(volatile unsigned*)&g_bar_gen = gen + 1;
        } else {
            while (*(volatile unsigned*)&g_bar_gen == gen) { __nanosleep(32); }
        }
        __threadfence();
    }
    __syncthreads();
}

// ---------------------------------------------------------------------------
// Kernel 1: row sums of squares; zero-init log_u / log_v.
// ---------------------------------------------------------------------------
__global__ __launch_bounds__(256) void sumsq_kernel(const float* __restrict__ x,
                                                    const float* __restrict__ y) {
    int warp = (blockIdx.x * 256 + threadIdx.x) >> 5;
    int lane = threadIdx.x & 31;
    int isx = (warp < BATCH * LSEQ);
    int r = isx ? warp : warp - BATCH * LSEQ;
    const float* src = isx ? x : y;
    const float4* p = (const float4*)(src + (size_t)r * DDIM);
    float s = 0.f;
#pragma unroll
    for (int t = 0; t < 2; t++) {
        float4 v = p[lane + 32 * t];
        s += v.x * v.x + v.y * v.y + v.z * v.z + v.w * v.w;
    }
#pragma unroll
    for (int o = 16; o; o >>= 1) s += __shfl_xor_sync(0xffffffffu, s, o);
    if (lane == 0) {
        if (isx) { g_x2[r] = s; g_lu[r] = 0.f; }
        else     { g_y2[r] = s; g_lv[r] = 0.f; }
    }
}

// ---------------------------------------------------------------------------
// Kernel 2: batched cost GEMM.  cost = sqrt(max(x2 + y2 - 2*x@y^T, 0)).
// 128x128 tile, BK=8, 256 threads, 8x8 microtile, packed f32x2 FMAs.
// Epilogue writes fp16 cost row-major AND transposed.
// ---------------------------------------------------------------------------
__global__ __launch_bounds__(256, 2) void cost_kernel(const float* __restrict__ x,
                                                      const float* __restrict__ y) {
    __shared__ __align__(16) float As[8][128];
    __shared__ __align__(16) float Bs[8][128];
    int b = blockIdx.z;
    int i0 = blockIdx.y * 128;
    int j0 = blockIdx.x * 128;
    int tid = threadIdx.x;
    int tx = tid & 15, ty = tid >> 4;
    const float* xb = x + (size_t)b * LSEQ * DDIM;
    const float* yb = y + (size_t)b * LSEQ * DDIM;
    int lr = tid >> 1;
    int lc = (tid & 1) * 4;

    ull acc[8][4];
#pragma unroll
    for (int ri = 0; ri < 8; ri++)
#pragma unroll
        for (int cj = 0; cj < 4; cj++) acc[ri][cj] = 0ull;

    for (int k0 = 0; k0 < DDIM; k0 += 8) {
        float4 av = *(const float4*)(xb + (size_t)(i0 + lr) * DDIM + k0 + lc);
        float4 bv = *(const float4*)(yb + (size_t)(j0 + lr) * DDIM + k0 + lc);
        __syncthreads();
        As[lc + 0][lr] = av.x; As[lc + 1][lr] = av.y;
        As[lc + 2][lr] = av.z; As[lc + 3][lr] = av.w;
        Bs[lc + 0][lr] = bv.x; Bs[lc + 1][lr] = bv.y;
        Bs[lc + 2][lr] = bv.z; Bs[lc + 3][lr] = bv.w;
        __syncthreads();
#pragma unroll
        for (int kk = 0; kk < 8; kk++) {
            float4 a0 = *(const float4*)&As[kk][ty * 8];
            float4 a1 = *(const float4*)&As[kk][ty * 8 + 4];
            float4 b0 = *(const float4*)&Bs[kk][tx * 8];
            float4 b1 = *(const float4*)&Bs[kk][tx * 8 + 4];
            ull bp[4];
            bp[0] = pack2(b0.x, b0.y); bp[1] = pack2(b0.z, b0.w);
            bp[2] = pack2(b1.x, b1.y); bp[3] = pack2(b1.z, b1.w);
            float a[8] = {a0.x, a0.y, a0.z, a0.w, a1.x, a1.y, a1.z, a1.w};
#pragma unroll
            for (int ri = 0; ri < 8; ri++) {
                ull ap = pack2(a[ri], a[ri]);
#pragma unroll
                for (int cj = 0; cj < 4; cj++) ffma2(acc[ri][cj], ap, bp[cj]);
            }
        }
    }

    float x2r[8], y2c[8];
#pragma unroll
    for (int ri = 0; ri < 8; ri++) x2r[ri] = g_x2[b * LSEQ + i0 + ty * 8 + ri];
#pragma unroll
    for (int c = 0; c < 8; c++)    y2c[c]  = g_y2[b * LSEQ + j0 + tx * 8 + c];

    __half hout[8][8];
#pragma unroll
    for (int ri = 0; ri < 8; ri++) {
        float out[8];
#pragma unroll
        for (int cj = 0; cj < 4; cj++) {
            float2 u = unpack2(acc[ri][cj]);
            out[2 * cj] = u.x; out[2 * cj + 1] = u.y;
        }
#pragma unroll
        for (int c = 0; c < 8; c++) {
            float d2 = x2r[ri] + y2c[c] - 2.f * out[c];
            hout[ri][c] = __float2half_rn(sqrtf(fmaxf(d2, 0.f)));
        }
        // row-major fp16 store (16 B)
        __half* dst = g_ch + ((size_t)b << 20) + (size_t)(i0 + ty * 8 + ri) * LSEQ + j0 + tx * 8;
        *(uint4*)dst = *(uint4*)&hout[ri][0];
    }
    // transposed fp16 stores (16 B each, scattered)
#pragma unroll
    for (int c = 0; c < 8; c++) {
        __half tcol[8];
#pragma unroll
        for (int ri = 0; ri < 8; ri++) tcol[ri] = hout[ri][c];
        __half* dst = g_ct + ((size_t)b << 20) + (size_t)(j0 + tx * 8 + c) * LSEQ + i0 + ty * 8;
        *(uint4*)dst = *(uint4*)&tcol[0];
    }
}

// LSE over one 1024-long fp16 line, warp-collective. Returns via lane 0.
// mat line base: 128 uint4 chunks of 8 halfs; vec: fp32 dual vector (lv or lu).
static __device__ __forceinline__ float warp_line_lse(const uint4* __restrict__ line,
                                                      const float4* __restrict__ vec,
                                                      int lane) {
    float m = -1e30f, s = 0.f;
#pragma unroll
    for (int t = 0; t < 2; t++) {   // two 16-element chunks per t-iter pair
        float a[16];
#pragma unroll
        for (int h = 0; h < 2; h++) {
            int ci = lane + 32 * (2 * t + h);
            uint4 q = line[ci];
            float4 va = __ldcg(&vec[2 * ci]);
            float4 vb = __ldcg(&vec[2 * ci + 1]);
            const __half2* hp = (const __half2*)&q;
            float2 f0 = __half22float2(hp[0]);
            float2 f1 = __half22float2(hp[1]);
            float2 f2 = __half22float2(hp[2]);
            float2 f3 = __half22float2(hp[3]);
            float* A = a + 8 * h;
            A[0] = fmaf(f0.x, -K2C, va.x); A[1] = fmaf(f0.y, -K2C, va.y);
            A[2] = fmaf(f1.x, -K2C, va.z); A[3] = fmaf(f1.y, -K2C, va.w);
            A[4] = fmaf(f2.x, -K2C, vb.x); A[5] = fmaf(f2.y, -K2C, vb.y);
            A[6] = fmaf(f3.x, -K2C, vb.z); A[7] = fmaf(f3.y, -K2C, vb.w);
        }
        float cm = a[0];
#pragma unroll
        for (int e = 1; e < 16; e++) cm = fmaxf(cm, a[e]);
        float M = fmaxf(m, cm);
        s *= ex2f(m - M);
#pragma unroll
        for (int e = 0; e < 16; e++) s += ex2f(a[e] - M);
        m = M;
    }
#pragma unroll
    for (int o = 16; o; o >>= 1) {
        float m2 = __shfl_xor_sync(0xffffffffu, m, o);
        float s2 = __shfl_xor_sync(0xffffffffu, s, o);
        float M = fmaxf(m, m2);
        s = s * ex2f(m - M) + s2 * ex2f(m2 - M);
        m = M;
    }
    return -10.f - (m + lg2f(s));
}

// ---------------------------------------------------------------------------
// Kernel 3: persistent Sinkhorn. Both passes are warp-per-line (row pass on
// g_ch, col pass on g_ct). 4096 warps x 4 lines each.
// ---------------------------------------------------------------------------
__global__ __launch_bounds__(NTHR, 4) void sinkhorn_persist(float* __restrict__ out) {
    __shared__ float smx[256];
    __shared__ float wsum[8];

    int tid = threadIdx.x;
    int w = tid >> 5;
    int lane = tid & 31;
    int wg = blockIdx.x * 8 + w;          // 0..4095

    for (int it = 0; it < 50; ++it) {
        // row pass: log_u[r] = -10 - LSE2_j(lv[j] - K2*C[r,j])
#pragma unroll 1
        for (int k = 0; k < 4; ++k) {
            int row = wg + 4096 * k;
            int b = row >> 10;
            float r = warp_line_lse((const uint4*)(g_ch + ((size_t)row << 10)),
                                    (const float4*)(g_lv + (b << 10)), lane);
            if (lane == 0) g_lu[row] = r;
        }
        grid_barrier();
        // col pass: log_v[c] = -10 - LSE2_i(lu[i] - K2*C[i,c])  (via C^T)
#pragma unroll 1
        for (int k = 0; k < 4; ++k) {
            int col = wg + 4096 * k;
            int b = col >> 10;
            float r = warp_line_lse((const uint4*)(g_ct + ((size_t)col << 10)),
                                    (const float4*)(g_lu + (b << 10)), lane);
            if (lane == 0) g_lv[col] = r;
        }
        grid_barrier();
    }

    // transport sum: warp-per-line on g_ch, block partials
    {
        float s = 0.f;
#pragma unroll 1
        for (int k = 0; k < 4; ++k) {
            int row = wg + 4096 * k;
            int b = row >> 10;
            float luI = __ldcg(&g_lu[row]);
            const uint4* line = (const uint4*)(g_ch + ((size_t)row << 10));
            const float4* v4 = (const float4*)(g_lv + (b << 10));
#pragma unroll 4
            for (int ci = lane; ci < 128; ci += 32) {
                uint4 q = line[ci];
                float4 va = __ldcg(&v4[2 * ci]);
                float4 vb = __ldcg(&v4[2 * ci + 1]);
                const __half2* hp = (const __half2*)&q;
                float2 f0 = __half22float2(hp[0]);
                float2 f1 = __half22float2(hp[1]);
                float2 f2 = __half22float2(hp[2]);
                float2 f3 = __half22float2(hp[3]);
                s += ex2f(fmaf(f0.x, -K2C, luI + va.x)) * f0.x;
                s += ex2f(fmaf(f0.y, -K2C, luI + va.y)) * f0.y;
                s += ex2f(fmaf(f1.x, -K2C, luI + va.z)) * f1.x;
                s += ex2f(fmaf(f1.y, -K2C, luI + va.w)) * f1.y;
                s += ex2f(fmaf(f2.x, -K2C, luI + vb.x)) * f2.x;
                s += ex2f(fmaf(f2.y, -K2C, luI + vb.y)) * f2.y;
                s += ex2f(fmaf(f3.x, -K2C, luI + vb.z)) * f3.x;
                s += ex2f(fmaf(f3.y, -K2C, luI + vb.w)) * f3.y;
            }
        }
#pragma unroll
        for (int o = 16; o; o >>= 1) s += __shfl_xor_sync(0xffffffffu, s, o);
        if (lane == 0) wsum[w] = s;
        __syncthreads();
        if (tid == 0) {
            float t = 0.f;
#pragma unroll
            for (int i = 0; i < 8; i++) t += wsum[i];
            g_part[blockIdx.x] = t;
        }
    }
    grid_barrier();

    if (blockIdx.x == 0) {
        float s = 0.f;
        for (int i = tid; i < NBLK; i += 256) s += __ldcg(&g_part[i]);
        smx[tid] = s;
        __syncthreads();
        for (int o = 128; o; o >>= 1) {
            if (tid < o) smx[tid] += smx[tid + o];
            __syncthreads();
        }
        if (tid == 0) out[0] = smx[0] * (1.f / 16.f);
    }
}

// ---------------------------------------------------------------------------
extern "C" void kernel_launch(void* const* d_in, const int* in_sizes, int n_in,
                              void* d_out, int out_size) {
    const float* x = (const float*)d_in[0];
    const float* y = (const float*)d_in[1];
    float* out = (float*)d_out;

    sumsq_kernel<<<4096, 256>>>(x, y);
    cost_kernel<<<dim3(8, 8, 16), 256>>>(x, y);
    sinkhorn_persist<<<NBLK, NTHR>>>(out);
}

// round 7
// speedup vs baseline: 1.3394x; 1.3394x over previous
#include <cuda_runtime.h>
#include <cuda_fp16.h>
#include <math.h>

// Sinkhorn distance: B=16, Lx=Ly=1024, D=256, eps=0.1, 50 iters.
// Log-domain in log2 units: lk2 = -cost*(10/ln2), log_mu2 = log_nu2 = -10.
// Cost matrix stored fp16 TWICE (row-major + transposed) so both sweep
// directions are warp-per-contiguous-line. The dual vector (lv or lu) is
// staged per-block in shared memory with a swizzle that makes the inner-loop
// reads lane-contiguous LDS.64 (conflict-free) -> vec causes ~0 L2 traffic.
// All 50 iterations + transport + reduce in ONE persistent kernel.

#define BATCH 16
#define LSEQ  1024
#define DDIM  256
#define K2C   14.426950408889634f   // 10 / ln(2)
#define NBLK  512
#define NTHR  256

__device__ __half g_ch[(size_t)BATCH * LSEQ * LSEQ];  // 32 MB row-major cost
__device__ __half g_ct[(size_t)BATCH * LSEQ * LSEQ];  // 32 MB transposed cost
__device__ float g_x2[BATCH * LSEQ];
__device__ float g_y2[BATCH * LSEQ];
__device__ float g_lu[BATCH * LSEQ];
__device__ float g_lv[BATCH * LSEQ];
__device__ float g_part[NBLK];
__device__ unsigned g_bar_cnt = 0;
__device__ unsigned g_bar_gen = 0;

static __device__ __forceinline__ float ex2f(float x) {
    float r; asm("ex2.approx.ftz.f32 %0, %1;" : "=f"(r) : "f"(x)); return r;
}
static __device__ __forceinline__ float lg2f(float x) {
    float r; asm("lg2.approx.ftz.f32 %0, %1;" : "=f"(r) : "f"(x)); return r;
}

typedef unsigned long long ull;
static __device__ __forceinline__ ull pack2(float lo, float hi) {
    ull r; asm("mov.b64 %0, {%1, %2};" : "=l"(r) : "f"(lo), "f"(hi)); return r;
}
static __device__ __forceinline__ float2 unpack2(ull v) {
    float2 r; asm("mov.b64 {%0, %1}, %2;" : "=f"(r.x), "=f"(r.y) : "l"(v)); return r;
}
static __device__ __forceinline__ void ffma2(ull& d, ull a, ull b) {
    asm("fma.rn.f32x2 %0, %1, %2, %0;" : "+l"(d) : "l"(a), "l"(b));
}

// Sense-reversing grid barrier (512 blocks; launch_bounds(256,4) -> 592 slots).
static __device__ __forceinline__ void grid_barrier() {
    __syncthreads();
    if (threadIdx.x == 0) {
        __threadfence();
        unsigned gen = *(volatile unsigned*)&g_bar_gen;
        unsigned prev = atomicAdd(&g_bar_cnt, 1u);
        if (prev == NBLK - 1) {
            g_bar_cnt = 0;
            __threadfence();
            *(volatile unsigned*)&g_bar_gen = gen + 1;
        } else {
            while (*(volatile unsigned*)&g_bar_gen == gen) { __nanosleep(32); }
        }
        __threadfence();
    }
    __syncthreads();
}

// ---------------------------------------------------------------------------
// Kernel 1: row sums of squares; zero-init log_u / log_v.
// ---------------------------------------------------------------------------
__global__ __launch_bounds__(256) void sumsq_kernel(const float* __restrict__ x,
                                                    const float* __restrict__ y) {
    int warp = (blockIdx.x * 256 + threadIdx.x) >> 5;
    int lane = threadIdx.x & 31;
    int isx = (warp < BATCH * LSEQ);
    int r = isx ? warp : warp - BATCH * LSEQ;
    const float* src = isx ? x : y;
    const float4* p = (const float4*)(src + (size_t)r * DDIM);
    float s = 0.f;
#pragma unroll
    for (int t = 0; t < 2; t++) {
        float4 v = p[lane + 32 * t];
        s += v.x * v.x + v.y * v.y + v.z * v.z + v.w * v.w;
    }
#pragma unroll
    for (int o = 16; o; o >>= 1) s += __shfl_xor_sync(0xffffffffu, s, o);
    if (lane == 0) {
        if (isx) { g_x2[r] = s; g_lu[r] = 0.f; }
        else     { g_y2[r] = s; g_lv[r] = 0.f; }
    }
}

// ---------------------------------------------------------------------------
// Kernel 2: batched cost GEMM.  cost = sqrt(max(x2 + y2 - 2*x@y^T, 0)).
// 128x128 tile, BK=8, 256 threads, 8x8 microtile, packed f32x2 FMAs.
// Epilogue writes fp16 cost row-major AND transposed.
// ---------------------------------------------------------------------------
__global__ __launch_bounds__(256, 2) void cost_kernel(const float* __restrict__ x,
                                                      const float* __restrict__ y) {
    __shared__ __align__(16) float As[8][128];
    __shared__ __align__(16) float Bs[8][128];
    int b = blockIdx.z;
    int i0 = blockIdx.y * 128;
    int j0 = blockIdx.x * 128;
    int tid = threadIdx.x;
    int tx = tid & 15, ty = tid >> 4;
    const float* xb = x + (size_t)b * LSEQ * DDIM;
    const float* yb = y + (size_t)b * LSEQ * DDIM;
    int lr = tid >> 1;
    int lc = (tid & 1) * 4;

    ull acc[8][4];
#pragma unroll
    for (int ri = 0; ri < 8; ri++)
#pragma unroll
        for (int cj = 0; cj < 4; cj++) acc[ri][cj] = 0ull;

    for (int k0 = 0; k0 < DDIM; k0 += 8) {
        float4 av = *(const float4*)(xb + (size_t)(i0 + lr) * DDIM + k0 + lc);
        float4 bv = *(const float4*)(yb + (size_t)(j0 + lr) * DDIM + k0 + lc);
        __syncthreads();
        As[lc + 0][lr] = av.x; As[lc + 1][lr] = av.y;
        As[lc + 2][lr] = av.z; As[lc + 3][lr] = av.w;
        Bs[lc + 0][lr] = bv.x; Bs[lc + 1][lr] = bv.y;
        Bs[lc + 2][lr] = bv.z; Bs[lc + 3][lr] = bv.w;
        __syncthreads();
#pragma unroll
        for (int kk = 0; kk < 8; kk++) {
            float4 a0 = *(const float4*)&As[kk][ty * 8];
            float4 a1 = *(const float4*)&As[kk][ty * 8 + 4];
            float4 b0 = *(const float4*)&Bs[kk][tx * 8];
            float4 b1 = *(const float4*)&Bs[kk][tx * 8 + 4];
            ull bp[4];
            bp[0] = pack2(b0.x, b0.y); bp[1] = pack2(b0.z, b0.w);
            bp[2] = pack2(b1.x, b1.y); bp[3] = pack2(b1.z, b1.w);
            float a[8] = {a0.x, a0.y, a0.z, a0.w, a1.x, a1.y, a1.z, a1.w};
#pragma unroll
            for (int ri = 0; ri < 8; ri++) {
                ull ap = pack2(a[ri], a[ri]);
#pragma unroll
                for (int cj = 0; cj < 4; cj++) ffma2(acc[ri][cj], ap, bp[cj]);
            }
        }
    }

    float x2r[8], y2c[8];
#pragma unroll
    for (int ri = 0; ri < 8; ri++) x2r[ri] = g_x2[b * LSEQ + i0 + ty * 8 + ri];
#pragma unroll
    for (int c = 0; c < 8; c++)    y2c[c]  = g_y2[b * LSEQ + j0 + tx * 8 + c];

    __half hout[8][8];
#pragma unroll
    for (int ri = 0; ri < 8; ri++) {
        float out[8];
#pragma unroll
        for (int cj = 0; cj < 4; cj++) {
            float2 u = unpack2(acc[ri][cj]);
            out[2 * cj] = u.x; out[2 * cj + 1] = u.y;
        }
#pragma unroll
        for (int c = 0; c < 8; c++) {
            float d2 = x2r[ri] + y2c[c] - 2.f * out[c];
            hout[ri][c] = __float2half_rn(sqrtf(fmaxf(d2, 0.f)));
        }
        __half* dst = g_ch + ((size_t)b << 20) + (size_t)(i0 + ty * 8 + ri) * LSEQ + j0 + tx * 8;
        *(uint4*)dst = *(uint4*)&hout[ri][0];
    }
#pragma unroll
    for (int c = 0; c < 8; c++) {
        __half tcol[8];
#pragma unroll
        for (int ri = 0; ri < 8; ri++) tcol[ri] = hout[ri][c];
        __half* dst = g_ct + ((size_t)b << 20) + (size_t)(j0 + tx * 8 + c) * LSEQ + i0 + ty * 8;
        *(uint4*)dst = *(uint4*)&tcol[0];
    }
}

// ---------------------------------------------------------------------------
// Shared-vec staging swizzle: slv2[(j&3)*128 + (j>>2)] = pair j of the 1024
// float vector (pair j = elements 2j,2j+1). Inner loop: chunk ci (8 halfs at
// elements 8ci..8ci+7) pairs with slv2[e*128+ci], e=0..3 — lane-contiguous
// LDS.64, conflict-free.
// ---------------------------------------------------------------------------
static __device__ __forceinline__ void stage_vec(float2* slv2, const float* vec) {
#pragma unroll
    for (int j = threadIdx.x; j < 512; j += NTHR) {
        float2 p = __ldcg(((const float2*)vec) + j);
        slv2[(j & 3) * 128 + (j >> 2)] = p;
    }
}

// LSE over one 1024-long fp16 line; vec from swizzled shared. Warp-collective.
static __device__ __forceinline__ float warp_line_lse(const uint4* __restrict__ line,
                                                      const float2* __restrict__ slv2,
                                                      int lane) {
    float m = -1e30f, s = 0.f;
#pragma unroll
    for (int t = 0; t < 2; t++) {
        float a[16];
#pragma unroll
        for (int h = 0; h < 2; h++) {
            int ci = lane + 32 * (2 * t + h);
            uint4 q = line[ci];
            float2 p0 = slv2[ci];
            float2 p1 = slv2[128 + ci];
            float2 p2 = slv2[256 + ci];
            float2 p3 = slv2[384 + ci];
            const __half2* hp = (const __half2*)&q;
            float2 f0 = __half22float2(hp[0]);
            float2 f1 = __half22float2(hp[1]);
            float2 f2 = __half22float2(hp[2]);
            float2 f3 = __half22float2(hp[3]);
            float* A = a + 8 * h;
            A[0] = fmaf(f0.x, -K2C, p0.x); A[1] = fmaf(f0.y, -K2C, p0.y);
            A[2] = fmaf(f1.x, -K2C, p1.x); A[3] = fmaf(f1.y, -K2C, p1.y);
            A[4] = fmaf(f2.x, -K2C, p2.x); A[5] = fmaf(f2.y, -K2C, p2.y);
            A[6] = fmaf(f3.x, -K2C, p3.x); A[7] = fmaf(f3.y, -K2C, p3.y);
        }
        float cm = a[0];
#pragma unroll
        for (int e = 1; e < 16; e++) cm = fmaxf(cm, a[e]);
        float M = fmaxf(m, cm);
        s *= ex2f(m - M);
#pragma unroll
        for (int e = 0; e < 16; e++) s += ex2f(a[e] - M);
        m = M;
    }
#pragma unroll
    for (int o = 16; o; o >>= 1) {
        float m2 = __shfl_xor_sync(0xffffffffu, m, o);
        float s2 = __shfl_xor_sync(0xffffffffu, s, o);
        float M = fmaxf(m, m2);
        s = s * ex2f(m - M) + s2 * ex2f(m2 - M);
        m = M;
    }
    return -10.f - (m + lg2f(s));
}

// ---------------------------------------------------------------------------
// Kernel 3: persistent Sinkhorn. Each block owns one 32-line group within one
// batch per pass: block g -> batch g>>5, lines (g&31)*32 + [0,32). 8 warps x
// 4 lines. Vec staged in shared once per pass per block.
// ---------------------------------------------------------------------------
__global__ __launch_bounds__(NTHR, 4) void sinkhorn_persist(float* __restrict__ out) {
    __shared__ __align__(16) float2 slv2[512];
    __shared__ float smx[256];
    __shared__ float wsum[8];

    int tid = threadIdx.x;
    int w = tid >> 5;
    int lane = tid & 31;
    int b = blockIdx.x >> 5;                    // batch
    int lbase = (blockIdx.x & 31) * 32;         // first line in group
    const float* lvb = g_lv + (b << 10);
    const float* lub = g_lu + (b << 10);

    for (int it = 0; it < 50; ++it) {
        // row pass: log_u[r] = -10 - LSE2_j(lv[j] - K2*C[r,j])
        stage_vec(slv2, lvb);
        __syncthreads();
#pragma unroll 1
        for (int k = 0; k < 4; ++k) {
            int row = (b << 10) + lbase + w * 4 + k;
            float r = warp_line_lse((const uint4*)(g_ch + ((size_t)row << 10)), slv2, lane);
            if (lane == 0) g_lu[row] = r;
        }
        grid_barrier();
        // col pass: log_v[c] = -10 - LSE2_i(lu[i] - K2*C[i,c])  (via C^T)
        stage_vec(slv2, lub);
        __syncthreads();
#pragma unroll 1
        for (int k = 0; k < 4; ++k) {
            int col = (b << 10) + lbase + w * 4 + k;
            float r = warp_line_lse((const uint4*)(g_ct + ((size_t)col << 10)), slv2, lane);
            if (lane == 0) g_lv[col] = r;
        }
        grid_barrier();
    }

    // transport sum: sum_ij 2^(lu_i + lv_j - K2*C) * C, block partials
    {
        stage_vec(slv2, lvb);
        __syncthreads();
        float s = 0.f;
#pragma unroll 1
        for (int k = 0; k < 4; ++k) {
            int row = (b << 10) + lbase + w * 4 + k;
            float luI = __ldcg(&g_lu[row]);
            const uint4* line = (const uint4*)(g_ch + ((size_t)row << 10));
#pragma unroll 4
            for (int ci = lane; ci < 128; ci += 32) {
                uint4 q = line[ci];
                float2 p0 = slv2[ci];
                float2 p1 = slv2[128 + ci];
                float2 p2 = slv2[256 + ci];
                float2 p3 = slv2[384 + ci];
                const __half2* hp = (const __half2*)&q;
                float2 f0 = __half22float2(hp[0]);
                float2 f1 = __half22float2(hp[1]);
                float2 f2 = __half22float2(hp[2]);
                float2 f3 = __half22float2(hp[3]);
                s += ex2f(fmaf(f0.x, -K2C, luI + p0.x)) * f0.x;
                s += ex2f(fmaf(f0.y, -K2C, luI + p0.y)) * f0.y;
                s += ex2f(fmaf(f1.x, -K2C, luI + p1.x)) * f1.x;
                s += ex2f(fmaf(f1.y, -K2C, luI + p1.y)) * f1.y;
                s += ex2f(fmaf(f2.x, -K2C, luI + p2.x)) * f2.x;
                s += ex2f(fmaf(f2.y, -K2C, luI + p2.y)) * f2.y;
                s += ex2f(fmaf(f3.x, -K2C, luI + p3.x)) * f3.x;
                s += ex2f(fmaf(f3.y, -K2C, luI + p3.y)) * f3.y;
            }
        }
#pragma unroll
        for (int o = 16; o; o >>= 1) s += __shfl_xor_sync(0xffffffffu, s, o);
        if (lane == 0) wsum[w] = s;
        __syncthreads();
        if (tid == 0) {
            float t = 0.f;
#pragma unroll
            for (int i = 0; i < 8; i++) t += wsum[i];
            g_part[blockIdx.x] = t;
        }
    }
    grid_barrier();

    if (blockIdx.x == 0) {
        float s = 0.f;
        for (int i = tid; i < NBLK; i += 256) s += __ldcg(&g_part[i]);
        smx[tid] = s;
        __syncthreads();
        for (int o = 128; o; o >>= 1) {
            if (tid < o) smx[tid] += smx[tid + o];
            __syncthreads();
        }
        if (tid == 0) out[0] = smx[0] * (1.f / 16.f);
    }
}

// ---------------------------------------------------------------------------
extern "C" void kernel_launch(void* const* d_in, const int* in_sizes, int n_in,
                              void* d_out, int out_size) {
    const float* x = (const float*)d_in[0];
    const float* y = (const float*)d_in[1];
    float* out = (float*)d_out;

    sumsq_kernel<<<4096, 256>>>(x, y);
    cost_kernel<<<dim3(8, 8, 16), 256>>>(x, y);
    sinkhorn_persist<<<NBLK, NTHR>>>(out);
}